// round 14
// baseline (speedup 1.0000x reference)
#include <cuda_runtime.h>
#include <cuda_fp16.h>
#include <cstdint>

// Problem constants (fixed by the dataset)
#define NMAX   100000
#define EMAX   1600000
#define F0     128
#define F1     64
#define F2     41
#define F2P    48   // padded stride for layer-2 features
#define CAP    64   // fixed bucket capacity per node (max deg ~40 for Poisson(16))

// ---------------- device scratch (no allocations allowed) ----------------
__device__ int    g_deg[NMAX];
__device__ int    g_colsrc[(size_t)NMAX * CAP];   // slotted adjacency, 25.6MB
__device__ __half g_h1s[(size_t)NMAX * F1];       // fp16: dinv * (x @ W1)
__device__ __half g_h2s[(size_t)NMAX * F2P];      // fp16: dinv * (h1 @ W2), padded

__device__ __forceinline__ uint32_t smem_u32(const void* p) {
    uint32_t a;
    asm("{ .reg .u64 t; cvta.to.shared.u64 t, %1; cvt.u32.u64 %0, t; }" : "=r"(a) : "l"(p));
    return a;
}

#define LDSM4(r0, r1, r2, r3, addr) \
    asm volatile("ldmatrix.sync.aligned.m8n8.x4.shared.b16 {%0,%1,%2,%3}, [%4];" \
                 : "=r"(r0), "=r"(r1), "=r"(r2), "=r"(r3) : "r"(addr))

#define MMA16816(c, a0, a1, a2, a3, b0, b1) \
    asm volatile("mma.sync.aligned.m16n8k16.row.col.f32.f16.f16.f32 " \
                 "{%0,%1,%2,%3},{%4,%5,%6,%7},{%8,%9},{%0,%1,%2,%3};" \
                 : "+f"((c)[0]), "+f"((c)[1]), "+f"((c)[2]), "+f"((c)[3]) \
                 : "r"(a0), "r"(a1), "r"(a2), "r"(a3), "r"(b0), "r"(b1))

// ---------------- zero degrees ----------------
__global__ void k_zero(int n) {
    int i = blockIdx.x * blockDim.x + threadIdx.x;
    if (i < n) g_deg[i] = 0;
}

// ---------------- hist + direct slotted scatter ----------------
__global__ void k_hist(const int* __restrict__ src, const int* __restrict__ dst, int e) {
    int i = blockIdx.x * blockDim.x + threadIdx.x;
    int e4 = e >> 2;
    if (i < e4) {
        int4 d = ((const int4*)dst)[i];
        int4 s = ((const int4*)src)[i];
        int p0 = atomicAdd(&g_deg[d.x], 1);
        int p1 = atomicAdd(&g_deg[d.y], 1);
        int p2 = atomicAdd(&g_deg[d.z], 1);
        int p3 = atomicAdd(&g_deg[d.w], 1);
        if (p0 < CAP) g_colsrc[(size_t)d.x * CAP + p0] = s.x;
        if (p1 < CAP) g_colsrc[(size_t)d.y * CAP + p1] = s.y;
        if (p2 < CAP) g_colsrc[(size_t)d.z * CAP + p2] = s.z;
        if (p3 < CAP) g_colsrc[(size_t)d.w * CAP + p3] = s.w;
    }
    if (i == 0) {
        for (int j = e4 * 4; j < e; j++) {
            int p = atomicAdd(&g_deg[dst[j]], 1);
            if (p < CAP) g_colsrc[(size_t)dst[j] * CAP + p] = src[j];
        }
    }
}

// ---------------- layer-1 fp16 tensor-core GEMM (mma.sync m16n8k16) ---------------------
// g_h1s[M x 64] (fp16) = dinv[row] * (A[M x 128] @ W1[128 x 64])
__global__ void __launch_bounds__(256)
mma_gemm1(const float* __restrict__ Aext, const float* __restrict__ Bm, int M) {
    constexpr int KTOT = F0, NPAD = 64, NSRC = F1;
    constexpr int SA = KTOT + 8;
    constexpr int KT = KTOT / 16;
    constexpr int NT = NPAD / 8;
    extern __shared__ __half sh[];
    __half* As = sh;                      // [128][SA]
    __half* Bs = sh + 128 * SA;           // [NPAD][SA] (B^T: row n, col k)

    int tid = threadIdx.x, lane = tid & 31, warp = tid >> 5;
    int row0 = blockIdx.x * 128;

    // ---- fill A tile: strength-reduced addressing; 2 batches of 8 LDG.128 ----
    {
        int rb = tid >> 5;               // base row 0..7
        int q  = tid & 31;               // float4 column 0..31
        const float4* ap = (const float4*)Aext + (size_t)(row0 + rb) * 32 + q;
        __half* sp = As + rb * SA + q * 4;
        #pragma unroll
        for (int h = 0; h < 2; h++) {
            float4 v[8];
            #pragma unroll
            for (int l = 0; l < 8; l++) {
                int gr = row0 + rb + (h * 8 + l) * 8;
                v[l] = (gr < M) ? __ldg(ap + (size_t)(h * 8 + l) * 8 * 32)
                                : make_float4(0.f, 0.f, 0.f, 0.f);
            }
            #pragma unroll
            for (int l = 0; l < 8; l++) {
                __half2 h0 = __floats2half2_rn(v[l].x, v[l].y);
                __half2 h1 = __floats2half2_rn(v[l].z, v[l].w);
                uint2 pk;
                pk.x = *(uint32_t*)&h0;
                pk.y = *(uint32_t*)&h1;
                *(uint2*)(sp + (h * 8 + l) * 8 * SA) = pk;
            }
        }
    }
    // ---- fill B tile (transpose to [n][k]) ----
    for (int vi = tid; vi < KTOT * NPAD; vi += 256) {
        int k = vi / NPAD, nn = vi % NPAD;
        float v = (nn < NSRC) ? __ldg(&Bm[(size_t)k * NSRC + nn]) : 0.f;
        Bs[nn * SA + k] = __float2half_rn(v);
    }
    __syncthreads();

    float c[NT][4];
    #pragma unroll
    for (int i = 0; i < NT; i++)
        #pragma unroll
        for (int j = 0; j < 4; j++) c[i][j] = 0.f;

    uint32_t aBase = smem_u32(As) +
        (uint32_t)(((warp * 16) + (lane & 7) + ((lane >> 3) & 1) * 8) * SA
                   + ((lane >> 4) & 1) * 8) * 2;
    uint32_t bBase = smem_u32(Bs) +
        (uint32_t)(((lane & 7) + ((lane >> 4) & 1) * 8) * SA
                   + ((lane >> 3) & 1) * 8) * 2;

    #pragma unroll
    for (int kt = 0; kt < KT; kt++) {
        int k0 = kt * 16;
        uint32_t a0, a1, a2, a3;
        LDSM4(a0, a1, a2, a3, aBase + k0 * 2);
        #pragma unroll
        for (int p = 0; p < NT / 2; p++) {
            uint32_t b0, b1, b2, b3;
            LDSM4(b0, b1, b2, b3, bBase + (uint32_t)(p * 16 * SA + k0) * 2);
            MMA16816(c[2 * p], a0, a1, a2, a3, b0, b1);
            MMA16816(c[2 * p + 1], a0, a1, a2, a3, b2, b3);
        }
    }

    // ---- epilogue: dinv scale (inline rsqrt), fp16 store ----
    int g = lane >> 2, t = lane & 3;
    int r1 = row0 + warp * 16 + g;
    int r2 = r1 + 8;
    float d1 = (r1 < M) ? rsqrtf((float)(g_deg[r1] + 1)) : 0.f;
    float d2 = (r2 < M) ? rsqrtf((float)(g_deg[r2] + 1)) : 0.f;
    #pragma unroll
    for (int nt = 0; nt < NT; nt++) {
        int col = nt * 8 + t * 2;
        if (r1 < M) {
            __half2 h = __floats2half2_rn(d1 * c[nt][0], d1 * c[nt][1]);
            *(__half2*)(g_h1s + (size_t)r1 * NPAD + col) = h;
        }
        if (r2 < M) {
            __half2 h = __floats2half2_rn(d2 * c[nt][2], d2 * c[nt][3]);
            *(__half2*)(g_h1s + (size_t)r2 * NPAD + col) = h;
        }
    }
}

// ---------------- fused: gather layer 1 + bias/relu + layer-2 GEMM ----------------------
// Block = 512 threads = 16 warps = 16 nodes. Each warp gathers one node's h1 (64 cols as
// half2/lane), writes tile to smem; warps 0..2 then run the 16x48x64 MMA and store h2s.
__global__ void __launch_bounds__(512)
k_gather1_gemm2(const float* __restrict__ b1, const float* __restrict__ W2, int n) {
    constexpr int SA2 = F1 + 8;   // 72 halves per row
    __shared__ alignas(16) __half hA[16][SA2];       // h1o tile (relu'd)
    __shared__ alignas(16) __half hB[F2P][SA2];      // W2^T [n][k]

    int tid = threadIdx.x, lane = tid & 31, warp = tid >> 5;
    int node0 = blockIdx.x * 16;
    int w = node0 + warp;

    // ---- load W2 tile (transposed, zero-padded) ----
    for (int vi = tid; vi < F1 * F2P; vi += 512) {
        int k = vi / F2P, nn = vi % F2P;
        float v = (nn < F2) ? __ldg(&W2[(size_t)k * F2 + nn]) : 0.f;
        hB[nn][k] = __float2half_rn(v);
    }

    // ---- gather: one warp per node ----
    if (w < n) {
        int deg = g_deg[w];
        if (deg > CAP) deg = CAP;
        const int* __restrict__ cs = g_colsrc + (size_t)w * CAP;
        const __half2* __restrict__ hp = (const __half2*)g_h1s;

        int idxA = __ldg(&cs[lane]);
        int idxB = (deg > 32) ? __ldg(&cs[32 + lane]) : 0;
        float2 self = __half22float2(__ldg(&hp[w * 32 + lane]));

        float ax = 0.f, ay = 0.f;
        int j = 0;
        for (; j + 8 <= deg; j += 8) {
            int word = (j < 32) ? idxA : idxB;
            int b = j & 31;
            int s0 = __shfl_sync(0xffffffffu, word, b + 0);
            int s1 = __shfl_sync(0xffffffffu, word, b + 1);
            int s2 = __shfl_sync(0xffffffffu, word, b + 2);
            int s3 = __shfl_sync(0xffffffffu, word, b + 3);
            int s4 = __shfl_sync(0xffffffffu, word, b + 4);
            int s5 = __shfl_sync(0xffffffffu, word, b + 5);
            int s6 = __shfl_sync(0xffffffffu, word, b + 6);
            int s7 = __shfl_sync(0xffffffffu, word, b + 7);
            float2 v0 = __half22float2(__ldg(&hp[s0 * 32 + lane]));
            float2 v1 = __half22float2(__ldg(&hp[s1 * 32 + lane]));
            float2 v2 = __half22float2(__ldg(&hp[s2 * 32 + lane]));
            float2 v3 = __half22float2(__ldg(&hp[s3 * 32 + lane]));
            float2 v4 = __half22float2(__ldg(&hp[s4 * 32 + lane]));
            float2 v5 = __half22float2(__ldg(&hp[s5 * 32 + lane]));
            float2 v6 = __half22float2(__ldg(&hp[s6 * 32 + lane]));
            float2 v7 = __half22float2(__ldg(&hp[s7 * 32 + lane]));
            ax += ((v0.x + v1.x) + (v2.x + v3.x)) + ((v4.x + v5.x) + (v6.x + v7.x));
            ay += ((v0.y + v1.y) + (v2.y + v3.y)) + ((v4.y + v5.y) + (v6.y + v7.y));
        }
        for (; j < deg; j++) {
            int word = (j < 32) ? idxA : idxB;
            int s = __shfl_sync(0xffffffffu, word, j & 31);
            float2 v = __half22float2(__ldg(&hp[s * 32 + lane]));
            ax += v.x; ay += v.y;
        }
        float di = rsqrtf((float)(deg + 1));
        float ox = fmaf(di, ax + self.x, __ldg(&b1[2 * lane]));
        float oy = fmaf(di, ay + self.y, __ldg(&b1[2 * lane + 1]));
        ox = fmaxf(ox, 0.f);
        oy = fmaxf(oy, 0.f);
        ((__half2*)hA[warp])[lane] = __floats2half2_rn(ox, oy);
    } else {
        ((__half2*)hA[warp])[lane] = __half2half2(__float2half(0.f));
    }
    __syncthreads();

    // ---- mma: warps 0..2 each compute a 16-col slice of the 16x48 output ----
    if (warp < 3) {
        float c[2][4] = {{0.f, 0.f, 0.f, 0.f}, {0.f, 0.f, 0.f, 0.f}};
        uint32_t aBase = smem_u32(hA) +
            (uint32_t)(((lane & 7) + ((lane >> 3) & 1) * 8) * SA2
                       + ((lane >> 4) & 1) * 8) * 2;
        uint32_t bBase = smem_u32(hB) +
            (uint32_t)(((lane & 7) + ((lane >> 4) & 1) * 8) * SA2
                       + ((lane >> 3) & 1) * 8) * 2
            + (uint32_t)(warp * 16 * SA2) * 2;
        #pragma unroll
        for (int kt = 0; kt < F1 / 16; kt++) {
            int k0 = kt * 16;
            uint32_t a0, a1, a2, a3, b0, b1r, b2, b3;
            LDSM4(a0, a1, a2, a3, aBase + k0 * 2);
            LDSM4(b0, b1r, b2, b3, bBase + k0 * 2);
            MMA16816(c[0], a0, a1, a2, a3, b0, b1r);
            MMA16816(c[1], a0, a1, a2, a3, b2, b3);
        }
        int g = lane >> 2, t = lane & 3;
        int r1 = node0 + g;
        int r2 = r1 + 8;
        float d1 = (r1 < n) ? rsqrtf((float)(min(g_deg[r1], CAP) * 0 + g_deg[r1] + 1)) : 0.f;
        float d2 = (r2 < n) ? rsqrtf((float)(g_deg[r2] + 1)) : 0.f;
        int colb = warp * 16 + t * 2;
        if (r1 < n) {
            __half2 h0 = __floats2half2_rn(d1 * c[0][0], d1 * c[0][1]);
            __half2 h1 = __floats2half2_rn(d1 * c[1][0], d1 * c[1][1]);
            *(__half2*)(g_h2s + (size_t)r1 * F2P + colb) = h0;
            *(__half2*)(g_h2s + (size_t)r1 * F2P + colb + 8) = h1;
        }
        if (r2 < n) {
            __half2 h0 = __floats2half2_rn(d2 * c[0][2], d2 * c[0][3]);
            __half2 h1 = __floats2half2_rn(d2 * c[1][2], d2 * c[1][3]);
            *(__half2*)(g_h2s + (size_t)r2 * F2P + colb) = h0;
            *(__half2*)(g_h2s + (size_t)r2 * F2P + colb + 8) = h1;
        }
    }
}

// ---------------- gather layer 2: warp per node; lanes 24..31 duplicate lane 23 ----------
__global__ void k_gather2(const float* __restrict__ b2, float* __restrict__ out, int n) {
    int w = (blockIdx.x * blockDim.x + threadIdx.x) >> 5;
    if (w >= n) return;
    int lane = threadIdx.x & 31;
    int deg = g_deg[w];
    if (deg > CAP) deg = CAP;
    const int* __restrict__ cs = g_colsrc + (size_t)w * CAP;
    const __half2* __restrict__ hp = (const __half2*)g_h2s;
    int cl = (lane < F2P / 2) ? lane : (F2P / 2 - 1);  // keep all lanes for shfl

    int idxA = __ldg(&cs[lane]);
    int idxB = (deg > 32) ? __ldg(&cs[32 + lane]) : 0;
    float2 self = __half22float2(__ldg(&hp[w * (F2P / 2) + cl]));

    float ax = 0.f, ay = 0.f;
    int j = 0;
    for (; j + 8 <= deg; j += 8) {
        int word = (j < 32) ? idxA : idxB;
        int b = j & 31;
        int s0 = __shfl_sync(0xffffffffu, word, b + 0);
        int s1 = __shfl_sync(0xffffffffu, word, b + 1);
        int s2 = __shfl_sync(0xffffffffu, word, b + 2);
        int s3 = __shfl_sync(0xffffffffu, word, b + 3);
        int s4 = __shfl_sync(0xffffffffu, word, b + 4);
        int s5 = __shfl_sync(0xffffffffu, word, b + 5);
        int s6 = __shfl_sync(0xffffffffu, word, b + 6);
        int s7 = __shfl_sync(0xffffffffu, word, b + 7);
        float2 v0 = __half22float2(__ldg(&hp[s0 * (F2P / 2) + cl]));
        float2 v1 = __half22float2(__ldg(&hp[s1 * (F2P / 2) + cl]));
        float2 v2 = __half22float2(__ldg(&hp[s2 * (F2P / 2) + cl]));
        float2 v3 = __half22float2(__ldg(&hp[s3 * (F2P / 2) + cl]));
        float2 v4 = __half22float2(__ldg(&hp[s4 * (F2P / 2) + cl]));
        float2 v5 = __half22float2(__ldg(&hp[s5 * (F2P / 2) + cl]));
        float2 v6 = __half22float2(__ldg(&hp[s6 * (F2P / 2) + cl]));
        float2 v7 = __half22float2(__ldg(&hp[s7 * (F2P / 2) + cl]));
        ax += ((v0.x + v1.x) + (v2.x + v3.x)) + ((v4.x + v5.x) + (v6.x + v7.x));
        ay += ((v0.y + v1.y) + (v2.y + v3.y)) + ((v4.y + v5.y) + (v6.y + v7.y));
    }
    for (; j < deg; j++) {
        int word = (j < 32) ? idxA : idxB;
        int s = __shfl_sync(0xffffffffu, word, j & 31);
        float2 v = __half22float2(__ldg(&hp[s * (F2P / 2) + cl]));
        ax += v.x; ay += v.y;
    }
    if (lane < F2P / 2) {
        float di = rsqrtf((float)(deg + 1));
        int c0 = 2 * lane, c1 = 2 * lane + 1;
        if (c0 < F2) out[w * F2 + c0] = fmaf(di, ax + self.x, b2[c0]);
        if (c1 < F2) out[w * F2 + c1] = fmaf(di, ay + self.y, b2[c1]);
    }
}

// ---------------- launcher ----------------
extern "C" void kernel_launch(void* const* d_in, const int* in_sizes, int n_in,
                              void* d_out, int out_size) {
    const float* x  = (const float*)d_in[0];
    const int*   ei = (const int*)d_in[1];
    const float* W1 = (const float*)d_in[2];
    const float* b1 = (const float*)d_in[3];
    const float* W2 = (const float*)d_in[4];
    const float* b2 = (const float*)d_in[5];
    float* out = (float*)d_out;

    int n = in_sizes[0] / F0;     // 100000
    int e = in_sizes[1] / 2;      // 1600000
    const int* src = ei;
    const int* dst = ei + e;

    constexpr int SMEM1 = (128 * (F0 + 8) + 64 * (F0 + 8)) * 2;    // 52224
    cudaFuncSetAttribute(mma_gemm1,
                         cudaFuncAttributeMaxDynamicSharedMemorySize, SMEM1);

    k_zero<<<(n + 511) / 512, 512>>>(n);
    k_hist<<<((e >> 2) + 255) / 256, 256>>>(src, dst, e);

    // layer 1: h1s = fp16( dinv * (x @ W1) )   [tensor cores]
    mma_gemm1<<<(n + 127) / 128, 256, SMEM1>>>(x, W1, n);

    // fused: gather1 + bias/relu + layer-2 GEMM -> h2s
    k_gather1_gemm2<<<(n + 15) / 16, 512>>>(b1, W2, n);

    // gather layer 2 -> out
    k_gather2<<<(n * 32 + 255) / 256, 256>>>(b2, out, n);
}

// round 17
// speedup vs baseline: 1.0919x; 1.0919x over previous
#include <cuda_runtime.h>
#include <cuda_fp16.h>
#include <cstdint>

// Problem constants (fixed by the dataset)
#define NMAX   100000
#define EMAX   1600000
#define F0     128
#define F1     64
#define F2     41
#define F2P    48   // padded stride for layer-2 features
#define CAP    64   // fixed bucket capacity per node (max deg ~40 for Poisson(16))

// ---------------- device scratch (no allocations allowed) ----------------
__device__ int    g_deg[NMAX];
__device__ int    g_colsrc[(size_t)NMAX * CAP];   // slotted adjacency, 25.6MB
__device__ __half g_h1s[(size_t)NMAX * F1];       // fp16: dinv * (x @ W1)
__device__ __half g_h1o[(size_t)NMAX * F1];       // fp16: relu(layer1 out)
__device__ __half g_h2s[(size_t)NMAX * F2P];      // fp16: dinv * (h1o @ W2), padded

__device__ __forceinline__ uint32_t smem_u32(const void* p) {
    uint32_t a;
    asm("{ .reg .u64 t; cvta.to.shared.u64 t, %1; cvt.u32.u64 %0, t; }" : "=r"(a) : "l"(p));
    return a;
}

#define LDSM4(r0, r1, r2, r3, addr) \
    asm volatile("ldmatrix.sync.aligned.m8n8.x4.shared.b16 {%0,%1,%2,%3}, [%4];" \
                 : "=r"(r0), "=r"(r1), "=r"(r2), "=r"(r3) : "r"(addr))

#define MMA16816(c, a0, a1, a2, a3, b0, b1) \
    asm volatile("mma.sync.aligned.m16n8k16.row.col.f32.f16.f16.f32 " \
                 "{%0,%1,%2,%3},{%4,%5,%6,%7},{%8,%9},{%0,%1,%2,%3};" \
                 : "+f"((c)[0]), "+f"((c)[1]), "+f"((c)[2]), "+f"((c)[3]) \
                 : "r"(a0), "r"(a1), "r"(a2), "r"(a3), "r"(b0), "r"(b1))

#define CP_ASYNC16(smem_addr, gptr) \
    asm volatile("cp.async.cg.shared.global [%0], [%1], 16;" \
                 :: "r"(smem_addr), "l"(gptr) : "memory")
#define CP_ASYNC_WAIT() \
    do { asm volatile("cp.async.commit_group;" ::: "memory"); \
         asm volatile("cp.async.wait_group 0;" ::: "memory"); } while (0)

// ---------------- zero degrees ----------------
__global__ void k_zero(int n) {
    int i = blockIdx.x * blockDim.x + threadIdx.x;
    if (i < n) g_deg[i] = 0;
}

// ---------------- hist + direct slotted scatter ----------------
__global__ void k_hist(const int* __restrict__ src, const int* __restrict__ dst, int e) {
    int i = blockIdx.x * blockDim.x + threadIdx.x;
    int e4 = e >> 2;
    if (i < e4) {
        int4 d = ((const int4*)dst)[i];
        int4 s = ((const int4*)src)[i];
        int p0 = atomicAdd(&g_deg[d.x], 1);
        int p1 = atomicAdd(&g_deg[d.y], 1);
        int p2 = atomicAdd(&g_deg[d.z], 1);
        int p3 = atomicAdd(&g_deg[d.w], 1);
        if (p0 < CAP) g_colsrc[(size_t)d.x * CAP + p0] = s.x;
        if (p1 < CAP) g_colsrc[(size_t)d.y * CAP + p1] = s.y;
        if (p2 < CAP) g_colsrc[(size_t)d.z * CAP + p2] = s.z;
        if (p3 < CAP) g_colsrc[(size_t)d.w * CAP + p3] = s.w;
    }
    if (i == 0) {
        for (int j = e4 * 4; j < e; j++) {
            int p = atomicAdd(&g_deg[dst[j]], 1);
            if (p < CAP) g_colsrc[(size_t)dst[j] * CAP + p] = src[j];
        }
    }
}

// ---------------- fp16 tensor-core GEMM (mma.sync m16n8k16) -----------------------------
// Ch[M x NPAD] (fp16) = dinv[row] * (A[M x KTOT] @ Bm[KTOT x NSRC]); n >= NSRC zero-padded
template<int KTOT, int NSRC, int NPAD, int LAYER>
__global__ void __launch_bounds__(256)
mma_gemm(const float* __restrict__ Aext, const float* __restrict__ Bm, int M) {
    constexpr int SA = KTOT + 8;          // half stride (conflict-free ldmatrix walk)
    constexpr int KT = KTOT / 16;
    constexpr int NT = NPAD / 8;
    extern __shared__ __half sh[];
    __half* As = sh;                      // [128][SA]
    __half* Bs = sh + 128 * SA;           // [NPAD][SA]  (B^T: row n, col k)

    int tid = threadIdx.x, lane = tid & 31, warp = tid >> 5;
    int row0 = blockIdx.x * 128;

    // ---- fill A tile ----
    if (LAYER == 1) {
        // strength-reduced addressing; 2 batches of 8 independent LDG.128
        int rb = tid >> 5;               // base row 0..7
        int q  = tid & 31;               // float4 column 0..31
        const float4* ap = (const float4*)Aext + (size_t)(row0 + rb) * 32 + q;
        __half* sp = As + rb * SA + q * 4;
        #pragma unroll
        for (int h = 0; h < 2; h++) {
            float4 v[8];
            #pragma unroll
            for (int l = 0; l < 8; l++) {
                int gr = row0 + rb + (h * 8 + l) * 8;
                v[l] = (gr < M) ? __ldg(ap + (size_t)(h * 8 + l) * 8 * 32)
                                : make_float4(0.f, 0.f, 0.f, 0.f);
            }
            #pragma unroll
            for (int l = 0; l < 8; l++) {
                __half2 h0 = __floats2half2_rn(v[l].x, v[l].y);
                __half2 h1 = __floats2half2_rn(v[l].z, v[l].w);
                uint2 pk;
                pk.x = *(uint32_t*)&h0;
                pk.y = *(uint32_t*)&h1;
                *(uint2*)(sp + (h * 8 + l) * 8 * SA) = pk;
            }
        }
    } else {
        // fp16 source: cp.async 16B, no register roundtrip
        const __half* Ah = g_h1o;
        uint32_t asb = smem_u32(As);
        #pragma unroll
        for (int vi = tid; vi < 128 * (KTOT / 8); vi += 256) {
            int r = vi / (KTOT / 8), q = vi % (KTOT / 8);
            int gr = row0 + r;
            if (gr < M) {
                CP_ASYNC16(asb + (uint32_t)(r * SA + q * 8) * 2,
                           Ah + (size_t)gr * KTOT + q * 8);
            } else {
                *(uint4*)(As + r * SA + q * 8) = make_uint4(0, 0, 0, 0);
            }
        }
    }
    // ---- fill B tile (transpose to [n][k]) ----
    for (int vi = tid; vi < KTOT * NPAD; vi += 256) {
        int k = vi / NPAD, nn = vi % NPAD;
        float v = (nn < NSRC) ? __ldg(&Bm[(size_t)k * NSRC + nn]) : 0.f;
        Bs[nn * SA + k] = __float2half_rn(v);
    }
    if (LAYER == 2) CP_ASYNC_WAIT();
    __syncthreads();

    float c[NT][4];
    #pragma unroll
    for (int i = 0; i < NT; i++)
        #pragma unroll
        for (int j = 0; j < 4; j++) c[i][j] = 0.f;

    uint32_t aBase = smem_u32(As) +
        (uint32_t)(((warp * 16) + (lane & 7) + ((lane >> 3) & 1) * 8) * SA
                   + ((lane >> 4) & 1) * 8) * 2;
    uint32_t bBase = smem_u32(Bs) +
        (uint32_t)(((lane & 7) + ((lane >> 4) & 1) * 8) * SA
                   + ((lane >> 3) & 1) * 8) * 2;

    #pragma unroll
    for (int kt = 0; kt < KT; kt++) {
        int k0 = kt * 16;
        uint32_t a0, a1, a2, a3;
        LDSM4(a0, a1, a2, a3, aBase + k0 * 2);
        #pragma unroll
        for (int p = 0; p < NT / 2; p++) {
            uint32_t b0, b1, b2, b3;
            LDSM4(b0, b1, b2, b3, bBase + (uint32_t)(p * 16 * SA + k0) * 2);
            MMA16816(c[2 * p], a0, a1, a2, a3, b0, b1);
            MMA16816(c[2 * p + 1], a0, a1, a2, a3, b2, b3);
        }
    }

    // ---- epilogue: dinv scale (inline rsqrt), fp16 store ----
    __half* Ch = (LAYER == 1) ? g_h1s : g_h2s;
    int g = lane >> 2, t = lane & 3;
    int r1 = row0 + warp * 16 + g;
    int r2 = r1 + 8;
    float d1 = (r1 < M) ? rsqrtf((float)(g_deg[r1] + 1)) : 0.f;
    float d2 = (r2 < M) ? rsqrtf((float)(g_deg[r2] + 1)) : 0.f;
    #pragma unroll
    for (int nt = 0; nt < NT; nt++) {
        int col = nt * 8 + t * 2;
        if (r1 < M) {
            __half2 h = __floats2half2_rn(d1 * c[nt][0], d1 * c[nt][1]);
            *(__half2*)(Ch + (size_t)r1 * NPAD + col) = h;
        }
        if (r2 < M) {
            __half2 h = __floats2half2_rn(d2 * c[nt][2], d2 * c[nt][3]);
            *(__half2*)(Ch + (size_t)r2 * NPAD + col) = h;
        }
    }
}

// ---------------- gather layer 1: warp per node; indices via shfl broadcast --------------
__global__ void k_gather1(const float* __restrict__ b1, int n) {
    int w = (blockIdx.x * blockDim.x + threadIdx.x) >> 5;
    if (w >= n) return;
    int lane = threadIdx.x & 31;
    int deg = g_deg[w];
    if (deg > CAP) deg = CAP;
    const int* __restrict__ cs = g_colsrc + (size_t)w * CAP;
    const __half2* __restrict__ hp = (const __half2*)g_h1s;

    int idxA = __ldg(&cs[lane]);
    int idxB = (deg > 32) ? __ldg(&cs[32 + lane]) : 0;
    float2 self = __half22float2(__ldg(&hp[w * 32 + lane]));

    float ax = 0.f, ay = 0.f;
    int j = 0;
    for (; j + 8 <= deg; j += 8) {
        int word = (j < 32) ? idxA : idxB;
        int b = j & 31;
        int s0 = __shfl_sync(0xffffffffu, word, b + 0);
        int s1 = __shfl_sync(0xffffffffu, word, b + 1);
        int s2 = __shfl_sync(0xffffffffu, word, b + 2);
        int s3 = __shfl_sync(0xffffffffu, word, b + 3);
        int s4 = __shfl_sync(0xffffffffu, word, b + 4);
        int s5 = __shfl_sync(0xffffffffu, word, b + 5);
        int s6 = __shfl_sync(0xffffffffu, word, b + 6);
        int s7 = __shfl_sync(0xffffffffu, word, b + 7);
        float2 v0 = __half22float2(__ldg(&hp[s0 * 32 + lane]));
        float2 v1 = __half22float2(__ldg(&hp[s1 * 32 + lane]));
        float2 v2 = __half22float2(__ldg(&hp[s2 * 32 + lane]));
        float2 v3 = __half22float2(__ldg(&hp[s3 * 32 + lane]));
        float2 v4 = __half22float2(__ldg(&hp[s4 * 32 + lane]));
        float2 v5 = __half22float2(__ldg(&hp[s5 * 32 + lane]));
        float2 v6 = __half22float2(__ldg(&hp[s6 * 32 + lane]));
        float2 v7 = __half22float2(__ldg(&hp[s7 * 32 + lane]));
        ax += ((v0.x + v1.x) + (v2.x + v3.x)) + ((v4.x + v5.x) + (v6.x + v7.x));
        ay += ((v0.y + v1.y) + (v2.y + v3.y)) + ((v4.y + v5.y) + (v6.y + v7.y));
    }
    for (; j < deg; j++) {
        int word = (j < 32) ? idxA : idxB;
        int s = __shfl_sync(0xffffffffu, word, j & 31);
        float2 v = __half22float2(__ldg(&hp[s * 32 + lane]));
        ax += v.x; ay += v.y;
    }
    float di = rsqrtf((float)(deg + 1));
    float ox = fmaf(di, ax + self.x, __ldg(&b1[2 * lane]));
    float oy = fmaf(di, ay + self.y, __ldg(&b1[2 * lane + 1]));
    ox = fmaxf(ox, 0.f);
    oy = fmaxf(oy, 0.f);
    ((__half2*)g_h1o)[w * 32 + lane] = __floats2half2_rn(ox, oy);
}

// ---------------- gather layer 2: warp per node; lanes 24..31 duplicate lane 23 ----------
__global__ void k_gather2(const float* __restrict__ b2, float* __restrict__ out, int n) {
    int w = (blockIdx.x * blockDim.x + threadIdx.x) >> 5;
    if (w >= n) return;
    int lane = threadIdx.x & 31;
    int deg = g_deg[w];
    if (deg > CAP) deg = CAP;
    const int* __restrict__ cs = g_colsrc + (size_t)w * CAP;
    const __half2* __restrict__ hp = (const __half2*)g_h2s;
    int cl = (lane < F2P / 2) ? lane : (F2P / 2 - 1);  // keep all lanes for shfl

    int idxA = __ldg(&cs[lane]);
    int idxB = (deg > 32) ? __ldg(&cs[32 + lane]) : 0;
    float2 self = __half22float2(__ldg(&hp[w * (F2P / 2) + cl]));

    float ax = 0.f, ay = 0.f;
    int j = 0;
    for (; j + 8 <= deg; j += 8) {
        int word = (j < 32) ? idxA : idxB;
        int b = j & 31;
        int s0 = __shfl_sync(0xffffffffu, word, b + 0);
        int s1 = __shfl_sync(0xffffffffu, word, b + 1);
        int s2 = __shfl_sync(0xffffffffu, word, b + 2);
        int s3 = __shfl_sync(0xffffffffu, word, b + 3);
        int s4 = __shfl_sync(0xffffffffu, word, b + 4);
        int s5 = __shfl_sync(0xffffffffu, word, b + 5);
        int s6 = __shfl_sync(0xffffffffu, word, b + 6);
        int s7 = __shfl_sync(0xffffffffu, word, b + 7);
        float2 v0 = __half22float2(__ldg(&hp[s0 * (F2P / 2) + cl]));
        float2 v1 = __half22float2(__ldg(&hp[s1 * (F2P / 2) + cl]));
        float2 v2 = __half22float2(__ldg(&hp[s2 * (F2P / 2) + cl]));
        float2 v3 = __half22float2(__ldg(&hp[s3 * (F2P / 2) + cl]));
        float2 v4 = __half22float2(__ldg(&hp[s4 * (F2P / 2) + cl]));
        float2 v5 = __half22float2(__ldg(&hp[s5 * (F2P / 2) + cl]));
        float2 v6 = __half22float2(__ldg(&hp[s6 * (F2P / 2) + cl]));
        float2 v7 = __half22float2(__ldg(&hp[s7 * (F2P / 2) + cl]));
        ax += ((v0.x + v1.x) + (v2.x + v3.x)) + ((v4.x + v5.x) + (v6.x + v7.x));
        ay += ((v0.y + v1.y) + (v2.y + v3.y)) + ((v4.y + v5.y) + (v6.y + v7.y));
    }
    for (; j < deg; j++) {
        int word = (j < 32) ? idxA : idxB;
        int s = __shfl_sync(0xffffffffu, word, j & 31);
        float2 v = __half22float2(__ldg(&hp[s * (F2P / 2) + cl]));
        ax += v.x; ay += v.y;
    }
    if (lane < F2P / 2) {
        float di = rsqrtf((float)(deg + 1));
        int c0 = 2 * lane, c1 = 2 * lane + 1;
        if (c0 < F2) out[w * F2 + c0] = fmaf(di, ax + self.x, b2[c0]);
        if (c1 < F2) out[w * F2 + c1] = fmaf(di, ay + self.y, b2[c1]);
    }
}

// ---------------- launcher ----------------
extern "C" void kernel_launch(void* const* d_in, const int* in_sizes, int n_in,
                              void* d_out, int out_size) {
    const float* x  = (const float*)d_in[0];
    const int*   ei = (const int*)d_in[1];
    const float* W1 = (const float*)d_in[2];
    const float* b1 = (const float*)d_in[3];
    const float* W2 = (const float*)d_in[4];
    const float* b2 = (const float*)d_in[5];
    float* out = (float*)d_out;

    int n = in_sizes[0] / F0;     // 100000
    int e = in_sizes[1] / 2;      // 1600000
    const int* src = ei;
    const int* dst = ei + e;

    int gblk = (n + 127) / 128;

    constexpr int SMEM1 = (128 * (F0 + 8) + 64 * (F0 + 8)) * 2;    // 52224
    constexpr int SMEM2 = (128 * (F1 + 8) + F2P * (F1 + 8)) * 2;   // 25344
    cudaFuncSetAttribute(mma_gemm<F0, F1, 64, 1>,
                         cudaFuncAttributeMaxDynamicSharedMemorySize, SMEM1);
    cudaFuncSetAttribute(mma_gemm<F1, F2, F2P, 2>,
                         cudaFuncAttributeMaxDynamicSharedMemorySize, SMEM2);

    k_zero<<<(n + 511) / 512, 512>>>(n);
    k_hist<<<((e >> 2) + 255) / 256, 256>>>(src, dst, e);

    // layer 1: h1s = fp16( dinv * (x @ W1) )   [tensor cores]
    mma_gemm<F0, F1, 64, 1><<<gblk, 256, SMEM1>>>(x, W1, n);

    // launch index 3 -> gets profiled next round
    k_gather1<<<(n * 32 + 255) / 256, 256>>>(b1, n);

    // layer 2: h2s = fp16( dinv * (h1o @ W2) ), padded to 48 cols   [tensor cores]
    mma_gemm<F1, F2, F2P, 2><<<gblk, 256, SMEM2>>>(nullptr, W2, n);

    k_gather2<<<(n * 32 + 255) / 256, 256>>>(b2, out, n);
}